// round 6
// baseline (speedup 1.0000x reference)
#include <cuda_runtime.h>

#define NN 50000
#define NE 800000
#define NBLK 196   // ceil(50000/256)

// ---------------- scratch (device globals; no allocation) ----------------
__device__ int g_degi[NN];
__device__ int g_off[NN + 1];
__device__ int g_fill[NN];
__device__ int g_bsum[256];
__device__ int g_boff[256];
__device__ __align__(16) float2 g_edge[NE];      // packed (src_as_float_bits, weight), CSR by dst
__device__ __align__(16) float  g_lin[NN * 64];  // [N][2*FO]: [0,FO)=h@Ws, [FO,2FO)=h@Wn
__device__ __align__(16) float  g_h[NN * 32];    // hidden activations

// ---------------- CSR build ----------------
__global__ void deg_kernel(const int* __restrict__ dst) {
    int e = blockIdx.x * blockDim.x + threadIdx.x;
    if (e < NE) atomicAdd(&g_degi[dst[e]], 1);
}

// exclusive scan, 2-level (256-wide blocks)
__global__ void scanA() {
    __shared__ int s[256];
    int i = blockIdx.x * 256 + threadIdx.x;
    int v = (i < NN) ? g_degi[i] : 0;
    s[threadIdx.x] = v;
    __syncthreads();
#pragma unroll
    for (int d = 1; d < 256; d <<= 1) {
        int t = (threadIdx.x >= d) ? s[threadIdx.x - d] : 0;
        __syncthreads();
        s[threadIdx.x] += t;
        __syncthreads();
    }
    if (i < NN) g_off[i] = s[threadIdx.x] - v;   // exclusive
    if (threadIdx.x == 255) g_bsum[blockIdx.x] = s[255];
}

__global__ void scanB() {
    __shared__ int s[256];
    int v = (threadIdx.x < NBLK) ? g_bsum[threadIdx.x] : 0;
    s[threadIdx.x] = v;
    __syncthreads();
#pragma unroll
    for (int d = 1; d < 256; d <<= 1) {
        int t = (threadIdx.x >= d) ? s[threadIdx.x - d] : 0;
        __syncthreads();
        s[threadIdx.x] += t;
        __syncthreads();
    }
    g_boff[threadIdx.x] = s[threadIdx.x] - v;    // exclusive
}

__global__ void scanC() {
    int i = blockIdx.x * 256 + threadIdx.x;
    if (i < NN) g_off[i] += g_boff[blockIdx.x];
    if (i == 0) g_off[NN] = NE;
}

__global__ void fill_kernel(const int* __restrict__ src, const int* __restrict__ dst,
                            const float* __restrict__ ew) {
    int e = blockIdx.x * blockDim.x + threadIdx.x;
    if (e >= NE) return;
    int d = dst[e];
    int pos = g_off[d] + atomicAdd(&g_fill[d], 1);
    g_edge[pos] = make_float2(__int_as_float(src[e]), ew[e]);
}

// ---------------- dense transform: lin[node][c] = h[node] . {Ws|Wn}[:,c] ----------------
template <int K, int FO, int NPI>
__global__ void gemm_kernel(const float* __restrict__ h,
                            const float* __restrict__ Ws,
                            const float* __restrict__ Wn,
                            float* __restrict__ outp) {
    constexpr int COLS = 2 * FO;
    __shared__ float sh[NPI * K];
    const int tid = threadIdx.x;
    const int c = tid % COLS;
    const int r = tid / COLS;

    float w[K];
    const float* W = (c < FO) ? Ws : Wn;
    const int cc = (c < FO) ? c : (c - FO);
#pragma unroll
    for (int k = 0; k < K; k++) w[k] = W[k * FO + cc];

    const int ntiles = (NN + NPI - 1) / NPI;
    for (int tile = blockIdx.x; tile < ntiles; tile += gridDim.x) {
        const int base = tile * NPI;
        __syncthreads();
        for (int idx = tid; idx < NPI * K; idx += blockDim.x) {
            const int rr = idx / K;
            const int kk = idx - rr * K;
            const int node = base + rr;
            sh[idx] = (node < NN) ? h[node * K + kk] : 0.0f;
        }
        __syncthreads();
        const int node = base + r;
        if (node < NN) {
            float acc = 0.0f;
#pragma unroll
            for (int k = 0; k < K; k += 4) {
                float4 hv = *reinterpret_cast<const float4*>(&sh[r * K + k]);
                acc += hv.x * w[k] + hv.y * w[k + 1] + hv.z * w[k + 2] + hv.w * w[k + 3];
            }
            outp[node * COLS + c] = acc;
        }
    }
}

// layer-2 transform: 2 output cols per node
__global__ void gemm2_kernel(const float* __restrict__ h,
                             const float* __restrict__ Ws,
                             const float* __restrict__ Wn,
                             float* __restrict__ outp) {
    __shared__ float ws[16], wn[16];
    if (threadIdx.x < 16) {
        ws[threadIdx.x] = Ws[threadIdx.x];
        wn[threadIdx.x] = Wn[threadIdx.x];
    }
    __syncthreads();
    int i = blockIdx.x * blockDim.x + threadIdx.x;
    if (i >= NN) return;
    float as = 0.0f, an = 0.0f;
#pragma unroll
    for (int k = 0; k < 16; k += 4) {
        float4 hv = *reinterpret_cast<const float4*>(h + i * 16 + k);
        as += hv.x * ws[k] + hv.y * ws[k + 1] + hv.z * ws[k + 2] + hv.w * ws[k + 3];
        an += hv.x * wn[k] + hv.y * wn[k + 1] + hv.z * wn[k + 2] + hv.w * wn[k + 3];
    }
    outp[i * 2] = as;
    outp[i * 2 + 1] = an;
}

// ---------------- fused gather + epilogue ----------------
// One warp per destination node. CPG = FO/4 column-groups per edge; ES = 32/CPG
// edges in flight per warp. Register accumulation; shfl reduce across edge slots;
// lanes [0,CPG) apply self + mean + bias (+tanh) and write a float4.
template <int FO, bool ACT>
__global__ void gather_kernel(const float* __restrict__ lin,
                              const float* __restrict__ b,
                              float* __restrict__ outp) {
    constexpr int CPG = FO / 4;
    constexpr int ES = 32 / CPG;
    const int warp = (blockIdx.x * blockDim.x + threadIdx.x) >> 5;
    const int lane = threadIdx.x & 31;
    if (warp >= NN) return;
    const int node = warp;
    const int start = g_off[node];
    const int end = g_off[node + 1];
    const int q = lane % CPG;
    const int eslot = lane / CPG;

    float a0 = 0.f, a1 = 0.f, a2 = 0.f, a3 = 0.f;
    for (int k = start + eslot; k < end; k += ES) {
        float2 ed = g_edge[k];
        const int s = __float_as_int(ed.x);
        const float w = ed.y;
        float4 v = *reinterpret_cast<const float4*>(lin + (size_t)s * (2 * FO) + FO + 4 * q);
        a0 += w * v.x; a1 += w * v.y; a2 += w * v.z; a3 += w * v.w;
    }
#pragma unroll
    for (int off = 16; off >= CPG; off >>= 1) {
        a0 += __shfl_down_sync(0xffffffffu, a0, off);
        a1 += __shfl_down_sync(0xffffffffu, a1, off);
        a2 += __shfl_down_sync(0xffffffffu, a2, off);
        a3 += __shfl_down_sync(0xffffffffu, a3, off);
    }
    if (lane < CPG) {
        const float invdeg = 1.0f / fmaxf((float)(end - start), 1.0f);
        const int j = 4 * q;
        float4 sv = *reinterpret_cast<const float4*>(lin + (size_t)node * (2 * FO) + j);
        float4 o;
        o.x = sv.x + a0 * invdeg + b[j + 0];
        o.y = sv.y + a1 * invdeg + b[j + 1];
        o.z = sv.z + a2 * invdeg + b[j + 2];
        o.w = sv.w + a3 * invdeg + b[j + 3];
        if (ACT) { o.x = tanhf(o.x); o.y = tanhf(o.y); o.z = tanhf(o.z); o.w = tanhf(o.w); }
        *reinterpret_cast<float4*>(outp + (size_t)node * FO + j) = o;
    }
}

// layer-2 fused gather (scalar), warp per node
__global__ void gather2_kernel(const float* __restrict__ lin,
                               const float* __restrict__ b,
                               float* __restrict__ outp) {
    const int warp = (blockIdx.x * blockDim.x + threadIdx.x) >> 5;
    const int lane = threadIdx.x & 31;
    if (warp >= NN) return;
    const int start = g_off[warp];
    const int end = g_off[warp + 1];
    float acc = 0.f;
    for (int k = start + lane; k < end; k += 32) {
        float2 ed = g_edge[k];
        acc += ed.y * lin[(size_t)__float_as_int(ed.x) * 2 + 1];
    }
#pragma unroll
    for (int off = 16; off >= 1; off >>= 1)
        acc += __shfl_down_sync(0xffffffffu, acc, off);
    if (lane == 0) {
        const float invdeg = 1.0f / fmaxf((float)(end - start), 1.0f);
        outp[warp] = lin[(size_t)warp * 2] + acc * invdeg + b[0];
    }
}

// ---------------- launch ----------------
extern "C" void kernel_launch(void* const* d_in, const int* in_sizes, int n_in,
                              void* d_out, int out_size) {
    (void)in_sizes; (void)n_in; (void)out_size;
    const float* b_z = (const float*)d_in[0];
    const int*   src = (const int*)d_in[1];
    const int*   dst = (const int*)d_in[2];
    const float* ew  = (const float*)d_in[3];
    const float* Ws0 = (const float*)d_in[4];
    const float* Wn0 = (const float*)d_in[5];
    const float* b0  = (const float*)d_in[6];
    const float* Ws1 = (const float*)d_in[7];
    const float* Wn1 = (const float*)d_in[8];
    const float* b1  = (const float*)d_in[9];
    const float* Ws2 = (const float*)d_in[10];
    const float* Wn2 = (const float*)d_in[11];
    const float* b2  = (const float*)d_in[12];
    float* outp = (float*)d_out;

    int *p_degi, *p_fill;
    float *p_lin, *p_h;
    cudaGetSymbolAddress((void**)&p_degi, g_degi);
    cudaGetSymbolAddress((void**)&p_fill, g_fill);
    cudaGetSymbolAddress((void**)&p_lin, g_lin);
    cudaGetSymbolAddress((void**)&p_h,   g_h);

    cudaStream_t s = 0;
    const int GWARP = (NN * 32 + 255) / 256;   // warp-per-node grids (6250)

    // ---- CSR build (once; reused by all 3 layers) ----
    cudaMemsetAsync(p_degi, 0, NN * sizeof(int), s);
    cudaMemsetAsync(p_fill, 0, NN * sizeof(int), s);
    deg_kernel<<<(NE + 255) / 256, 256, 0, s>>>(dst);
    scanA<<<NBLK, 256, 0, s>>>();
    scanB<<<1, 256, 0, s>>>();
    scanC<<<NBLK, 256, 0, s>>>();
    fill_kernel<<<(NE + 255) / 256, 256, 0, s>>>(src, dst, ew);

    // ---- layer 0: 64 -> 32, tanh ----
    gemm_kernel<64, 32, 4><<<592, 256, 0, s>>>(b_z, Ws0, Wn0, p_lin);
    gather_kernel<32, true><<<GWARP, 256, 0, s>>>(p_lin, b0, p_h);

    // ---- layer 1: 32 -> 16, tanh ----
    gemm_kernel<32, 16, 8><<<592, 256, 0, s>>>(p_h, Ws1, Wn1, p_lin);
    gather_kernel<16, true><<<GWARP, 256, 0, s>>>(p_lin, b1, p_h);

    // ---- layer 2: 16 -> 1, no activation ----
    gemm2_kernel<<<(NN + 255) / 256, 256, 0, s>>>(p_h, Ws2, Wn2, p_lin);
    gather2_kernel<<<GWARP, 256, 0, s>>>(p_lin, b2, outp);
}